// round 9
// baseline (speedup 1.0000x reference)
#include <cuda_runtime.h>
#include <cuda_bf16.h>
#include <math.h>

#define SS     16      // samples per group
#define CC     128     // channels
#define GNN    256     // groups per batch item
#define NR     9       // max instance rows (bg + 8 fg labels)
#define MAXG   32768   // scratch capacity (G = 8192 here)
#define GP     2       // groups per CTA
#define CPAD   129     // padded channel pitch in staged smem
#define NTHR   256

// per-group partial results (deterministic scratch, no atomics on values)
__device__ __align__(16) float g_gl[MAXG];
__device__ __align__(16) float g_gv[MAXG];
__device__ unsigned g_count = 0;   // last-CTA election counter (self-resetting)

// triangle pair LUT: p -> (i, j), j <= i, p = i(i+1)/2 + j, for instnum <= 9
__device__ __constant__ signed char TRI_I[45] = {
    0, 1,1, 2,2,2, 3,3,3,3, 4,4,4,4,4, 5,5,5,5,5,5,
    6,6,6,6,6,6,6, 7,7,7,7,7,7,7,7, 8,8,8,8,8,8,8,8,8 };
__device__ __constant__ signed char TRI_J[45] = {
    0, 0,1, 0,1,2, 0,1,2,3, 0,1,2,3,4, 0,1,2,3,4,5,
    0,1,2,3,4,5,6, 0,1,2,3,4,5,6,7, 0,1,2,3,4,5,6,7,8 };

__global__ void __launch_bounds__(NTHR) proposal_clloss_group_kernel(
    const int*   __restrict__ labs,    // [G*S]
    const float* __restrict__ feats,   // [bs, C, Gn, S]
    const int*   __restrict__ idxs,    // [G*S]
    const float* __restrict__ ctx,     // [C]
    float*       __restrict__ out,     // [1]
    int G)
{
    __shared__ float s_sf[GP * SS * CPAD];   // staged features, [gs][s][c]
    __shared__ float s_M[GP][NR][CC];        // instance-mean rows
    __shared__ float s_sim[GP][NR * NR];
    __shared__ int   s_order[GP][SS];        // samples sorted by instance row
    __shared__ int   s_start[GP][NR];
    __shared__ int   s_end[GP][NR];
    __shared__ float s_inv[GP][NR];
    __shared__ int   s_instnum[GP];
    __shared__ int   s_hasbg[GP];
    __shared__ unsigned s_last;

    const int tid   = threadIdx.x;
    const int warp  = tid >> 5;
    const int lane  = tid & 31;
    const int gbase = blockIdx.x * GP;

    // ----- issue coalesced feature loads early --------------------------
    // 2 adjacent groups: per channel c, GP*SS floats = 128 B contiguous,
    // 128-B aligned (g_in even). flat = c*8 + gs*4 + q; 1024 float4 total.
    const int    g_in = gbase % GNN;
    const size_t base = (size_t)(gbase - g_in) * (CC * SS) + (size_t)g_in * SS;

    float4 v[4];
    int    dst_c[4], dst_r[4];
    #pragma unroll
    for (int it = 0; it < 4; it++) {
        const int flat = it * NTHR + tid;
        const int c  = flat >> 3;
        const int r  = flat & 7;        // gs*4 + q
        dst_c[it] = c;
        dst_r[it] = r;
        const float* p = feats + base + (size_t)c * (GNN * SS)
                       + (r >> 2) * SS + (r & 3) * 4;
        v[it] = *reinterpret_cast<const float4*>(p);
    }
    const float ctx_c = __ldg(ctx + (tid & (CC - 1)));

    // ----- Phase A: per-group metadata, warp w handles group w ----------
    if (warp < GP) {
        const int g   = gbase + warp;
        const bool smp = (lane < SS);
        const int idx_v = smp ? idxs[g * SS + lane] : (0x40000000 + lane);
        const int lab_v = smp ? labs[g * SS + lane] : 0;

        const unsigned m_idx = __match_any_sync(0xffffffffu, idx_v);
        const bool first = ((m_idx & ((1u << lane) - 1u)) == 0u);
        const int u = __popc(__ballot_sync(0xffffffffu, first && smp));

        const bool valid  = smp && (lane < u);
        const int labcode = valid ? (lab_v + 1) : 31;   // 0..8 valid, 31 = none

        unsigned b[NR];
        int cnt[NR];
        #pragma unroll
        for (int vv = 0; vv < NR; vv++) {
            b[vv]   = __ballot_sync(0xffffffffu, labcode == vv);
            cnt[vv] = __popc(b[vv]);
        }
        unsigned pres = 0;
        #pragma unroll
        for (int vv = 0; vv < NR; vv++) pres |= (cnt[vv] ? 1u : 0u) << vv;
        int pr[NR + 1];
        pr[0] = 0;
        #pragma unroll
        for (int vv = 0; vv < NR; vv++) pr[vv + 1] = pr[vv] + cnt[vv];

        const int hasbg   = (int)(pres & 1u);
        const int instnum = __popc(pres >> 1) + 1;

        if (valid) {
            const int pos = pr[labcode] + __popc(b[labcode] & ((1u << lane) - 1u));
            s_order[warp][pos] = lane;
        }
        if (lane < NR) {
            s_start[warp][lane] = 0;
            s_end[warp][lane]   = 0;
            s_inv[warp][lane]   = 1.0f;
        }
        __syncwarp();
        if (lane < NR && cnt[lane] > 0) {
            const int r = (lane == 0) ? 0
                        : 1 + __popc((pres & ((1u << lane) - 1u)) >> 1);
            s_start[warp][r] = pr[lane];
            s_end[warp][r]   = pr[lane] + cnt[lane];
            s_inv[warp][r]   = 1.0f / (float)cnt[lane];
        }
        if (lane == 0) { s_instnum[warp] = instnum; s_hasbg[warp] = hasbg; }
    }

    // ----- stage features to smem (transposed [gs][s][c]) ----------------
    #pragma unroll
    for (int it = 0; it < 4; it++) {
        const int c  = dst_c[it];
        const int gs = dst_r[it] >> 2;
        const int q  = dst_r[it] & 3;
        float* d = s_sf + (gs * SS + q * 4) * CPAD + c;
        d[0 * CPAD] = v[it].x;
        d[1 * CPAD] = v[it].y;
        d[2 * CPAD] = v[it].z;
        d[3 * CPAD] = v[it].w;
    }
    __syncthreads();

    // ----- Phase B: per-channel instance means (segment gather) ----------
    {
        const int gs   = tid >> 7;        // 0..1
        const int c    = tid & (CC - 1);  // 0..127
        const int inum = s_instnum[gs];
        const float* fcol = s_sf + gs * SS * CPAD + c;
        for (int r = 0; r < inum; r++) {
            const int st = s_start[gs][r];
            const int en = s_end[gs][r];
            float x = 0.0f;
            for (int k = st; k < en; k++)
                x += fcol[s_order[gs][k] * CPAD];
            s_M[gs][r][c] = x * s_inv[gs][r];
        }
        if (!s_hasbg[gs])
            s_M[gs][0][c] = ctx_c;         // row 0 = context compensation
    }
    __syncthreads();

    // ----- Phase C: sim = (M M^T) / T  (4 warps per group) ---------------
    {
        const int gs   = warp & 1;
        const int sub  = warp >> 1;         // 0..3
        const int inum = s_instnum[gs];
        const int P = inum * (inum + 1) / 2;
        for (int p = sub; p < P; p += 4) {
            const int i = TRI_I[p];
            const int j = TRI_J[p];
            float pa = 0.0f;
            #pragma unroll
            for (int k = 0; k < 4; k++)
                pa += s_M[gs][i][lane + 32 * k] * s_M[gs][j][lane + 32 * k];
            #pragma unroll
            for (int o = 16; o; o >>= 1)
                pa += __shfl_xor_sync(0xffffffffu, pa, o);
            if (lane == 0) {
                const float x = pa * 5.0f;  // 1/T, T = 0.2
                s_sim[gs][i * NR + j] = x;
                s_sim[gs][j * NR + i] = x;
            }
        }
    }
    __syncthreads();

    // ----- Phase D: per-row logsumexp, group loss ------------------------
    if (warp < GP) {
        const int gs   = warp;
        const int inum = s_instnum[gs];
        float li = 0.0f;
        const int i = lane + 1;
        if (i < inum) {
            float mx = -3.402823466e38f;
            for (int j = 0; j < inum; j++)
                mx = fmaxf(mx, s_sim[gs][i * NR + j]);
            float sum = 0.0f;
            for (int j = 0; j < inum; j++)
                sum += __expf(s_sim[gs][i * NR + j] - mx);
            li = mx + __logf(sum) - s_sim[gs][i * NR + i];
        }
        #pragma unroll
        for (int o = 16; o; o >>= 1)
            li += __shfl_xor_sync(0xffffffffu, li, o);
        if (lane == 0) {
            const float gv = (inum >= 2) ? 1.0f : 0.0f;
            const float gl = (inum >= 2) ? li / (float)(inum - 1) : 0.0f;
            g_gl[gbase + gs] = gl * gv;
            g_gv[gbase + gs] = gv;
        }
    }

    // ----- tail: last CTA reduces all partials (deterministic) -----------
    __threadfence();
    __syncthreads();
    if (tid == 0) s_last = atomicAdd(&g_count, 1u);
    __syncthreads();
    if (s_last == (unsigned)(gridDim.x - 1)) {
        if (tid == 0) g_count = 0;          // reset for next launch

        __shared__ float sn[NTHR];
        __shared__ float sd[NTHR];
        const float4* pl = reinterpret_cast<const float4*>(g_gl);
        const float4* pv = reinterpret_cast<const float4*>(g_gv);
        const int nq = G >> 2;              // G multiple of 4
        float n = 0.0f, d = 0.0f;
        for (int i = tid; i < nq; i += NTHR) {
            const float4 a = pl[i];
            const float4 bq = pv[i];
            n += (a.x + a.y) + (a.z + a.w);
            d += (bq.x + bq.y) + (bq.z + bq.w);
        }
        sn[tid] = n;
        sd[tid] = d;
        __syncthreads();
        for (int s = NTHR / 2; s; s >>= 1) {
            if (tid < s) { sn[tid] += sn[tid + s]; sd[tid] += sd[tid + s]; }
            __syncthreads();
        }
        if (tid == 0) out[0] = sn[0] / sd[0] * 0.1f;
    }
}

extern "C" void kernel_launch(void* const* d_in, const int* in_sizes, int n_in,
                              void* d_out, int out_size)
{
    const int*   labs  = (const int*)  d_in[0];  // proposal_instance_mask [bs,Gn,S]
    const float* feats = (const float*)d_in[1];  // grouped_features [bs,C,Gn,S]
    const int*   idxs  = (const int*)  d_in[2];  // grouped_indices [bs,Gn,S]
    const float* ctx   = (const float*)d_in[3];  // context_compen [1,C]
    float*       out   = (float*)d_out;

    const int G = in_sizes[0] / SS;              // total group count (8192)

    proposal_clloss_group_kernel<<<G / GP, NTHR>>>(labs, feats, idxs, ctx, out, G);
}

// round 10
// speedup vs baseline: 1.1060x; 1.1060x over previous
#include <cuda_runtime.h>
#include <cuda_bf16.h>
#include <math.h>

#define SS     16      // samples per group
#define CC     128     // channels
#define GNN    256     // groups per batch item
#define NR     9       // max instance rows (bg + 8 fg labels)
#define MAXG   32768   // scratch capacity (G = 8192 here)
#define GP     2       // groups per CTA
#define CPAD   129     // padded channel pitch in staged smem
#define NTHR   256

// per-group packed partials: (gl*gv, gv) — deterministic scratch
__device__ __align__(16) float2 g_part[MAXG];

// triangle pair LUT: p -> (i, j), j <= i, p = i(i+1)/2 + j, for instnum <= 9
__device__ __constant__ signed char TRI_I[45] = {
    0, 1,1, 2,2,2, 3,3,3,3, 4,4,4,4,4, 5,5,5,5,5,5,
    6,6,6,6,6,6,6, 7,7,7,7,7,7,7,7, 8,8,8,8,8,8,8,8,8 };
__device__ __constant__ signed char TRI_J[45] = {
    0, 0,1, 0,1,2, 0,1,2,3, 0,1,2,3,4, 0,1,2,3,4,5,
    0,1,2,3,4,5,6, 0,1,2,3,4,5,6,7, 0,1,2,3,4,5,6,7,8 };

__global__ void __launch_bounds__(NTHR) proposal_clloss_group_kernel(
    const int*   __restrict__ labs,    // [G*S]
    const float* __restrict__ feats,   // [bs, C, Gn, S]
    const int*   __restrict__ idxs,    // [G*S]
    const float* __restrict__ ctx)     // [C]
{
    __shared__ float s_sf[GP * SS * CPAD];               // staged [gs][s][c]
    __shared__ __align__(16) float s_M[GP][NR][CC];      // instance-mean rows
    __shared__ float s_sim[GP][NR * NR];
    __shared__ int   s_order[GP][SS];                    // samples sorted by row
    __shared__ int   s_start[GP][NR];
    __shared__ int   s_end[GP][NR];
    __shared__ float s_inv[GP][NR];
    __shared__ int   s_instnum[GP];
    __shared__ int   s_hasbg[GP];

    const int tid   = threadIdx.x;
    const int warp  = tid >> 5;
    const int lane  = tid & 31;
    const int gbase = blockIdx.x * GP;

    // ----- issue coalesced feature loads early --------------------------
    // 2 adjacent groups: per channel c, GP*SS floats = 128 B contiguous,
    // 128-B aligned (g_in even). flat = c*8 + gs*4 + q; 1024 float4 total.
    const int    g_in = gbase % GNN;
    const size_t base = (size_t)(gbase - g_in) * (CC * SS) + (size_t)g_in * SS;

    float4 v[4];
    int    dst_c[4], dst_r[4];
    #pragma unroll
    for (int it = 0; it < 4; it++) {
        const int flat = it * NTHR + tid;
        const int c  = flat >> 3;
        const int r  = flat & 7;        // gs*4 + q
        dst_c[it] = c;
        dst_r[it] = r;
        const float* p = feats + base + (size_t)c * (GNN * SS)
                       + (r >> 2) * SS + (r & 3) * 4;
        v[it] = *reinterpret_cast<const float4*>(p);
    }
    const float ctx_c = __ldg(ctx + (tid & (CC - 1)));

    // ----- Phase A: per-group metadata, warp w handles group w ----------
    if (warp < GP) {
        const int g   = gbase + warp;
        const bool smp = (lane < SS);
        const int idx_v = smp ? idxs[g * SS + lane] : (0x40000000 + lane);
        const int lab_v = smp ? labs[g * SS + lane] : 0;

        const unsigned m_idx = __match_any_sync(0xffffffffu, idx_v);
        const bool first = ((m_idx & ((1u << lane) - 1u)) == 0u);
        const int u = __popc(__ballot_sync(0xffffffffu, first && smp));

        const bool valid  = smp && (lane < u);
        const int labcode = valid ? (lab_v + 1) : 31;   // 0..8 valid, 31 = none

        unsigned b[NR];
        int cnt[NR];
        #pragma unroll
        for (int vv = 0; vv < NR; vv++) {
            b[vv]   = __ballot_sync(0xffffffffu, labcode == vv);
            cnt[vv] = __popc(b[vv]);
        }
        unsigned pres = 0;
        #pragma unroll
        for (int vv = 0; vv < NR; vv++) pres |= (cnt[vv] ? 1u : 0u) << vv;
        int pr[NR + 1];
        pr[0] = 0;
        #pragma unroll
        for (int vv = 0; vv < NR; vv++) pr[vv + 1] = pr[vv] + cnt[vv];

        const int hasbg   = (int)(pres & 1u);
        const int instnum = __popc(pres >> 1) + 1;

        if (valid) {
            const int pos = pr[labcode] + __popc(b[labcode] & ((1u << lane) - 1u));
            s_order[warp][pos] = lane;
        }
        if (lane < NR) {
            s_start[warp][lane] = 0;
            s_end[warp][lane]   = 0;
            s_inv[warp][lane]   = 1.0f;
        }
        __syncwarp();
        if (lane < NR && cnt[lane] > 0) {
            const int r = (lane == 0) ? 0
                        : 1 + __popc((pres & ((1u << lane) - 1u)) >> 1);
            s_start[warp][r] = pr[lane];
            s_end[warp][r]   = pr[lane] + cnt[lane];
            s_inv[warp][r]   = 1.0f / (float)cnt[lane];
        }
        if (lane == 0) { s_instnum[warp] = instnum; s_hasbg[warp] = hasbg; }
    }

    // ----- stage features to smem (transposed [gs][s][c]) ----------------
    #pragma unroll
    for (int it = 0; it < 4; it++) {
        const int c  = dst_c[it];
        const int gs = dst_r[it] >> 2;
        const int q  = dst_r[it] & 3;
        float* d = s_sf + (gs * SS + q * 4) * CPAD + c;
        d[0 * CPAD] = v[it].x;
        d[1 * CPAD] = v[it].y;
        d[2 * CPAD] = v[it].z;
        d[3 * CPAD] = v[it].w;
    }
    __syncthreads();

    // ----- Phase B: per-channel instance means (segment gather) ----------
    {
        const int gs   = tid >> 7;        // 0..1
        const int c    = tid & (CC - 1);  // 0..127
        const int inum = s_instnum[gs];
        const float* fcol = s_sf + gs * SS * CPAD + c;
        for (int r = 0; r < inum; r++) {
            const int st = s_start[gs][r];
            const int en = s_end[gs][r];
            float x = 0.0f;
            for (int k = st; k < en; k++)
                x += fcol[s_order[gs][k] * CPAD];
            s_M[gs][r][c] = x * s_inv[gs][r];
        }
        if (!s_hasbg[gs])
            s_M[gs][0][c] = ctx_c;         // row 0 = context compensation
    }
    __syncthreads();

    // ----- Phase C: sim = (M M^T) / T  (4 warps per group, float4 LDS) ---
    {
        const int gs   = warp & 1;
        const int sub  = warp >> 1;         // 0..3
        const int inum = s_instnum[gs];
        const int P = inum * (inum + 1) / 2;
        for (int p = sub; p < P; p += 4) {
            const int i = TRI_I[p];
            const int j = TRI_J[p];
            const float4 a  = reinterpret_cast<const float4*>(s_M[gs][i])[lane];
            const float4 bb = reinterpret_cast<const float4*>(s_M[gs][j])[lane];
            float pa = a.x * bb.x + a.y * bb.y + a.z * bb.z + a.w * bb.w;
            #pragma unroll
            for (int o = 16; o; o >>= 1)
                pa += __shfl_xor_sync(0xffffffffu, pa, o);
            if (lane == 0) {
                const float x = pa * 5.0f;  // 1/T, T = 0.2
                s_sim[gs][i * NR + j] = x;
                s_sim[gs][j * NR + i] = x;
            }
        }
    }
    __syncthreads();

    // ----- Phase D: per-row logsumexp, group loss ------------------------
    if (warp < GP) {
        const int gs   = warp;
        const int inum = s_instnum[gs];
        float li = 0.0f;
        const int i = lane + 1;
        if (i < inum) {
            float mx = -3.402823466e38f;
            for (int j = 0; j < inum; j++)
                mx = fmaxf(mx, s_sim[gs][i * NR + j]);
            float sum = 0.0f;
            for (int j = 0; j < inum; j++)
                sum += __expf(s_sim[gs][i * NR + j] - mx);
            li = mx + __logf(sum) - s_sim[gs][i * NR + i];
        }
        #pragma unroll
        for (int o = 16; o; o >>= 1)
            li += __shfl_xor_sync(0xffffffffu, li, o);
        if (lane == 0) {
            const float gv = (inum >= 2) ? 1.0f : 0.0f;
            const float gl = (inum >= 2) ? li / (float)(inum - 1) : 0.0f;
            g_part[gbase + gs] = make_float2(gl * gv, gv);
        }
    }
}

__global__ void __launch_bounds__(1024) proposal_clloss_reduce_kernel(
    float* __restrict__ out, int G)
{
    __shared__ float sn[32];
    __shared__ float sd[32];
    const int tid  = threadIdx.x;
    const int warp = tid >> 5;
    const int lane = tid & 31;

    // G float2 entries = G/2 float4 (pairs of (gl,gv))
    const float4* p4 = reinterpret_cast<const float4*>(g_part);
    const int nq = G >> 1;                 // float4 count (G multiple of 2)
    float n = 0.0f, d = 0.0f;
    #pragma unroll 4
    for (int i = tid; i < nq; i += 1024) {
        const float4 x = p4[i];            // (gl0, gv0, gl1, gv1)
        n += x.x + x.z;
        d += x.y + x.w;
    }
    #pragma unroll
    for (int o = 16; o; o >>= 1) {
        n += __shfl_xor_sync(0xffffffffu, n, o);
        d += __shfl_xor_sync(0xffffffffu, d, o);
    }
    if (lane == 0) { sn[warp] = n; sd[warp] = d; }
    __syncthreads();
    if (warp == 0) {
        float nn = sn[lane];
        float dd = sd[lane];
        #pragma unroll
        for (int o = 16; o; o >>= 1) {
            nn += __shfl_xor_sync(0xffffffffu, nn, o);
            dd += __shfl_xor_sync(0xffffffffu, dd, o);
        }
        if (lane == 0) out[0] = nn / dd * 0.1f;
    }
}

extern "C" void kernel_launch(void* const* d_in, const int* in_sizes, int n_in,
                              void* d_out, int out_size)
{
    const int*   labs  = (const int*)  d_in[0];  // proposal_instance_mask [bs,Gn,S]
    const float* feats = (const float*)d_in[1];  // grouped_features [bs,C,Gn,S]
    const int*   idxs  = (const int*)  d_in[2];  // grouped_indices [bs,Gn,S]
    const float* ctx   = (const float*)d_in[3];  // context_compen [1,C]
    float*       out   = (float*)d_out;

    const int G = in_sizes[0] / SS;              // total group count (8192)

    proposal_clloss_group_kernel<<<G / GP, NTHR>>>(labs, feats, idxs, ctx);
    proposal_clloss_reduce_kernel<<<1, 1024>>>(out, G);
}